// round 1
// baseline (speedup 1.0000x reference)
#include <cuda_runtime.h>
#include <cstdint>

// Problem constants
#define BB 128
#define TT 256
#define II 256
#define HH 256
#define LL 4
#define SS 3
#define KK 256
#define MTOT (BB*TT)   // 32768 rows (m = b*T + t), matches flat x layout [B,T,I]

// Scratch: h_all[s][l][m][h]  (3*4*32768*256 floats = 384 MiB)
__device__ float g_h[(size_t)SS * LL * MTOT * HH];
__device__ float g_tabctx[255 * 3 * 3];  // ctx-score part, indexed [t_prev][s_prev][s']
__device__ float g_xproj[256 * 3];       // x-projection part + B*b_sel, indexed [tau][s']
__device__ int   g_cur[256];             // selected stack per output step

__device__ __forceinline__ float sigm(float v) { return 1.f / (1.f + __expf(-v)); }

// ---------------------------------------------------------------------------
// Fused GEMM + GRU gating:  h = gru(A @ W^T + b_ih, b_hh)
// A: [MTOT, 256] (x for layer 0, previous layer otherwise), W: [768, 256] per s.
// Tile: 128 rows x (32 h-cols x 3 gates), K-chunks of 32, register prefetch.
// ---------------------------------------------------------------------------
__global__ __launch_bounds__(256, 2)
void gru_gemm_kernel(const float* __restrict__ Xin,
                     const float* __restrict__ Wg, long long sWs,
                     const float* __restrict__ BIg, const float* __restrict__ BHg, int sBs,
                     int layer)
{
    __shared__ float As[32][132];   // [k][m], pad 4 (16B-aligned rows for LDS.128)
    __shared__ float Ws[32][100];   // [k][col], col<96, pad 4 (8B-aligned for LDS.64)

    const int s = blockIdx.z;
    const float* A = (layer == 0) ? Xin
                   : (g_h + (size_t)(s * LL + layer - 1) * MTOT * HH);
    float* O = g_h + (size_t)(s * LL + layer) * MTOT * HH;
    const float* W  = Wg  + (size_t)s * sWs;
    const float* BI = BIg + s * sBs;
    const float* BH = BHg + s * sBs;

    const int mBase = blockIdx.x * 128;
    const int hBase = blockIdx.y * 32;

    const int tid = threadIdx.x;
    const int tx = tid & 15;      // col group: cols 2*tx, 2*tx+1 per gate
    const int ty = tid >> 4;      // row group: rows ty*8 .. ty*8+7
    const int kq = tid & 7;       // k-quad for loading
    const int rr = tid >> 3;      // 0..31 row/wrow for loading

    float acc[8][6];
#pragma unroll
    for (int i = 0; i < 8; i++)
#pragma unroll
        for (int j = 0; j < 6; j++) acc[i][j] = 0.f;

    float4 aF[4]; float4 wF[3];

    // prefetch k-tile 0
    {
        const float* Ap = A + (size_t)(mBase + rr) * KK + kq * 4;
#pragma unroll
        for (int i = 0; i < 4; i++) aF[i] = *(const float4*)(Ap + (size_t)(32 * i) * KK);
        const float* Wp = W + (size_t)(hBase + rr) * KK + kq * 4;
#pragma unroll
        for (int i = 0; i < 3; i++) wF[i] = *(const float4*)(Wp + (size_t)(i * 256) * KK);
    }

    for (int kt = 0; kt < 8; ++kt) {
#pragma unroll
        for (int i = 0; i < 4; i++) {
            As[kq * 4 + 0][rr + 32 * i] = aF[i].x;
            As[kq * 4 + 1][rr + 32 * i] = aF[i].y;
            As[kq * 4 + 2][rr + 32 * i] = aF[i].z;
            As[kq * 4 + 3][rr + 32 * i] = aF[i].w;
        }
#pragma unroll
        for (int i = 0; i < 3; i++) {
            Ws[kq * 4 + 0][i * 32 + rr] = wF[i].x;
            Ws[kq * 4 + 1][i * 32 + rr] = wF[i].y;
            Ws[kq * 4 + 2][i * 32 + rr] = wF[i].z;
            Ws[kq * 4 + 3][i * 32 + rr] = wF[i].w;
        }
        __syncthreads();
        if (kt < 7) {
            const int k0 = (kt + 1) * 32;
            const float* Ap = A + (size_t)(mBase + rr) * KK + k0 + kq * 4;
#pragma unroll
            for (int i = 0; i < 4; i++) aF[i] = *(const float4*)(Ap + (size_t)(32 * i) * KK);
            const float* Wp = W + (size_t)(hBase + rr) * KK + k0 + kq * 4;
#pragma unroll
            for (int i = 0; i < 3; i++) wF[i] = *(const float4*)(Wp + (size_t)(i * 256) * KK);
        }
#pragma unroll
        for (int k = 0; k < 32; k++) {
            float4 a0 = *(const float4*)&As[k][ty * 8];
            float4 a1 = *(const float4*)&As[k][ty * 8 + 4];
            float2 w0 = *(const float2*)&Ws[k][tx * 2];
            float2 w1 = *(const float2*)&Ws[k][32 + tx * 2];
            float2 w2 = *(const float2*)&Ws[k][64 + tx * 2];
            float av[8] = {a0.x, a0.y, a0.z, a0.w, a1.x, a1.y, a1.z, a1.w};
            float wv[6] = {w0.x, w0.y, w1.x, w1.y, w2.x, w2.y};
#pragma unroll
            for (int i = 0; i < 8; i++)
#pragma unroll
                for (int j = 0; j < 6; j++) acc[i][j] += av[i] * wv[j];
        }
        __syncthreads();
    }

    // epilogue: GRU gating.  r=sig(gr+bhr), z=sig(gz+bhz), n=tanh(gn + r*bhn), out=(1-z)*n
#pragma unroll
    for (int i = 0; i < 8; i++) {
        const int m = mBase + ty * 8 + i;
        float2 o;
#pragma unroll
        for (int cc = 0; cc < 2; cc++) {
            const int h = hBase + tx * 2 + cc;
            float gr = acc[i][0 + cc] + __ldg(&BI[h])       + __ldg(&BH[h]);
            float gz = acc[i][2 + cc] + __ldg(&BI[256 + h]) + __ldg(&BH[256 + h]);
            float gn = acc[i][4 + cc] + __ldg(&BI[512 + h]);
            float r = sigm(gr);
            float z = sigm(gz);
            float n = 2.f * sigm(2.f * (gn + r * __ldg(&BH[512 + h]))) - 1.f;
            float hv = (1.f - z) * n;
            if (cc == 0) o.x = hv; else o.y = hv;
        }
        *(float2*)&O[(size_t)m * HH + hBase + tx * 2] = o;
    }
}

// ---------------------------------------------------------------------------
// Per-(t, s_prev): attention + context-score. Produces
// tabctx[t][s][s'] = sum_b sum_l softmax_l(attn)[b,l] * (h[b,l,:] . w_sel[s',:H])
// One block per (t, s); warp-per-(b,l) dot products, deterministic reductions.
// ---------------------------------------------------------------------------
__global__ __launch_bounds__(256)
void table_kernel(const float* __restrict__ hidden,
                  const float* __restrict__ w_lw,
                  const float* __restrict__ b_lw,
                  const float* __restrict__ w_sel)
{
    const int t = blockIdx.x;   // 0..254 (h of step t feeds selection at step t+1)
    const int s = blockIdx.y;
    const int tid = threadIdx.x;
    const int lane = tid & 31;
    const int wp = tid >> 5;

    __shared__ float ep[512][8];   // per (b,l): e[0..3] (energy pre-bias), p[4..6]
    __shared__ float red[4][3];

    // per-lane weight registers: 7 projection rows x 8 chunks
    float wr[7][8];
#pragma unroll
    for (int q = 0; q < 7; q++)
#pragma unroll
        for (int j = 0; j < 8; j++) {
            const int idx = lane + 32 * j;
            wr[q][j] = (q < 4) ? __ldg(&w_lw[q * 256 + idx])
                               : __ldg(&w_sel[(q - 4) * 512 + idx]);
        }

    for (int p = wp; p < 512; p += 8) {
        const int b = p >> 2, l = p & 3;
        const float* hr = g_h + ((size_t)(s * LL + l) * MTOT + (size_t)b * TT + t) * HH;
        float acc[7] = {0, 0, 0, 0, 0, 0, 0};
#pragma unroll
        for (int j = 0; j < 8; j++) {
            const float hv = __ldg(&hr[lane + 32 * j]);
#pragma unroll
            for (int q = 0; q < 7; q++) acc[q] += hv * wr[q][j];
        }
#pragma unroll
        for (int q = 0; q < 7; q++) {
#pragma unroll
            for (int off = 16; off; off >>= 1)
                acc[q] += __shfl_xor_sync(0xffffffffu, acc[q], off);
        }
        if (lane < 7) ep[p][lane] = acc[lane];
    }
    __syncthreads();

    float sc[3] = {0.f, 0.f, 0.f};
    if (tid < 128) {
        const int b = tid;
        float bl[4];
#pragma unroll
        for (int lp = 0; lp < 4; lp++) bl[lp] = __ldg(&b_lw[lp]);
        float attn[4];
#pragma unroll
        for (int l = 0; l < 4; l++) {
            float a = 0.f;
#pragma unroll
            for (int lp = 0; lp < 4; lp++)
                a += __ldg(&hidden[b * 16 + l * 4 + lp]) * (ep[b * 4 + l][lp] + bl[lp]);
            attn[l] = a;
        }
        const float mx = fmaxf(fmaxf(attn[0], attn[1]), fmaxf(attn[2], attn[3]));
        float ee[4], ssum = 0.f;
#pragma unroll
        for (int l = 0; l < 4; l++) { ee[l] = __expf(attn[l] - mx); ssum += ee[l]; }
        const float inv = 1.f / ssum;
#pragma unroll
        for (int l = 0; l < 4; l++) {
            const float a = ee[l] * inv;
#pragma unroll
            for (int q = 0; q < 3; q++) sc[q] += a * ep[b * 4 + l][4 + q];
        }
#pragma unroll
        for (int q = 0; q < 3; q++)
#pragma unroll
            for (int off = 16; off; off >>= 1)
                sc[q] += __shfl_xor_sync(0xffffffffu, sc[q], off);
        if (lane == 0) { red[wp][0] = sc[0]; red[wp][1] = sc[1]; red[wp][2] = sc[2]; }
    }
    __syncthreads();
    if (tid < 3) {
        const float v = red[0][tid] + red[1][tid] + red[2][tid] + red[3][tid];
        g_tabctx[(t * 3 + s) * 3 + tid] = v;
    }
}

// ---------------------------------------------------------------------------
// xproj[tau][s'] = (sum_b x[b,tau,:]) . w_sel[s', H:] + B*b_sel[s'], tau = 1..255
// ---------------------------------------------------------------------------
__global__ __launch_bounds__(256)
void xproj_kernel(const float* __restrict__ x,
                  const float* __restrict__ w_sel,
                  const float* __restrict__ b_sel)
{
    const int tau = blockIdx.x + 1;  // 1..255
    const int tid = threadIdx.x;
    const int lane = tid & 31, wp = tid >> 5;
    __shared__ float red[3][8];
    float xs = 0.f;
    const float* xp = x + (size_t)tau * II + tid;
#pragma unroll 4
    for (int b = 0; b < 128; b++) xs += __ldg(&xp[(size_t)b * TT * II]);
    float sc[3];
#pragma unroll
    for (int q = 0; q < 3; q++) sc[q] = xs * __ldg(&w_sel[q * 512 + 256 + tid]);
#pragma unroll
    for (int q = 0; q < 3; q++)
#pragma unroll
        for (int off = 16; off; off >>= 1)
            sc[q] += __shfl_xor_sync(0xffffffffu, sc[q], off);
    if (lane == 0) { red[0][wp] = sc[0]; red[1][wp] = sc[1]; red[2][wp] = sc[2]; }
    __syncthreads();
    if (tid < 3) {
        float v = 0.f;
#pragma unroll
        for (int w2 = 0; w2 < 8; w2++) v += red[tid][w2];
        g_xproj[tau * 3 + tid] = v + 128.f * __ldg(&b_sel[tid]);
    }
}

// ---------------------------------------------------------------------------
// Serial recurrence over the tiny transition table (shared memory, 1 thread).
// argmax ties resolve to the FIRST max (matches jnp.argmax).
// ---------------------------------------------------------------------------
__global__ void serial_kernel()
{
    __shared__ float tab[255 * 9];
    __shared__ float xp[256 * 3];
    const int tid = threadIdx.x;
    for (int i = tid; i < 255 * 9; i += 256) tab[i] = g_tabctx[i];
    for (int i = tid; i < 256 * 3; i += 256) xp[i] = g_xproj[i];
    __syncthreads();
    if (tid == 0) {
        g_cur[0] = 0;
        int cur = 0;
        for (int tau = 1; tau < 256; tau++) {
            const float* tv = &tab[((tau - 1) * 3 + cur) * 3];
            const float v0 = tv[0] + xp[tau * 3 + 0];
            const float v1 = tv[1] + xp[tau * 3 + 1];
            const float v2 = tv[2] + xp[tau * 3 + 2];
            int c = 0; float best = v0;
            if (v1 > best) { best = v1; c = 1; }
            if (v2 > best) { best = v2; c = 2; }
            cur = c; g_cur[tau] = c;
        }
    }
}

// ---------------------------------------------------------------------------
// Gather: outputs[b,t,:] = h_all[cur[t]][L-1][b*T+t][:]; tail = outputs[:,T-1,:]
// ---------------------------------------------------------------------------
__global__ __launch_bounds__(256)
void gather_kernel(float* __restrict__ out, long long n)
{
    const long long idx = (long long)blockIdx.x * 256 + threadIdx.x;
    if (idx >= n) return;
    const long long BTH = (long long)BB * TT * HH;
    int b, t, h;
    if (idx < BTH) {
        b = (int)(idx >> 16);                 // T*H = 65536
        const int r = (int)(idx & 65535);
        t = r >> 8; h = r & 255;
    } else {
        const long long j = idx - BTH;
        if (j >= (long long)BB * HH) { out[idx] = 0.f; return; }
        b = (int)(j >> 8); h = (int)(j & 255); t = TT - 1;
    }
    const int cur = g_cur[t];
    out[idx] = g_h[((size_t)(cur * LL + (LL - 1)) * MTOT + (size_t)b * TT + t) * HH + h];
}

// ---------------------------------------------------------------------------
extern "C" void kernel_launch(void* const* d_in, const int* in_sizes, int n_in,
                              void* d_out, int out_size)
{
    (void)in_sizes; (void)n_in;
    const float* x      = (const float*)d_in[0];
    const float* hidden = (const float*)d_in[1];
    const float* w_ih0  = (const float*)d_in[2];
    const float* b_ih0  = (const float*)d_in[3];
    const float* b_hh0  = (const float*)d_in[4];
    const float* w_ih   = (const float*)d_in[5];
    const float* b_ih   = (const float*)d_in[6];
    const float* b_hh   = (const float*)d_in[7];
    const float* w_lw   = (const float*)d_in[8];
    const float* b_lw   = (const float*)d_in[9];
    const float* w_sel  = (const float*)d_in[10];
    const float* b_sel  = (const float*)d_in[11];
    float* out = (float*)d_out;

    const dim3 gGemm(MTOT / 128, HH / 32, SS);

    // layer 0: A = x (same for all s), W = w_ih0[s]
    gru_gemm_kernel<<<gGemm, 256>>>(x, w_ih0, (long long)768 * 256,
                                    b_ih0, b_hh0, 768, 0);
    // layers 1..3: A = h_all[s][l-1], W = w_ih[s][l-1]
    for (int l = 1; l < LL; l++) {
        gru_gemm_kernel<<<gGemm, 256>>>(
            x,
            w_ih + (size_t)(l - 1) * 768 * 256, (long long)(LL - 1) * 768 * 256,
            b_ih + (size_t)(l - 1) * 768,
            b_hh + (size_t)(l - 1) * 768, (LL - 1) * 768,
            l);
    }

    xproj_kernel<<<255, 256>>>(x, w_sel, b_sel);
    table_kernel<<<dim3(255, 3), 256>>>(hidden, w_lw, b_lw, w_sel);
    serial_kernel<<<1, 256>>>();

    const long long n = (long long)out_size;
    const int nb = (int)((n + 255) / 256);
    gather_kernel<<<nb, 256>>>(out, n);
}

// round 3
// speedup vs baseline: 2.2337x; 2.2337x over previous
#include <cuda_runtime.h>
#include <cstdint>

// Problem constants
#define BB 128
#define TT 256
#define II 256
#define HH 256
#define LL 4
#define SS 3
#define KK 256
#define MTOT (BB*TT)

// Scratch
__device__ float g_h[(size_t)SS * LL * MTOT * HH];   // h_all[s][l][m][h]
__device__ float g_tabctx[255 * 3 * 3];
__device__ float g_xproj[256 * 3];
__device__ int   g_cur[256];

__device__ __forceinline__ uint32_t f2tf(float f) {
    uint32_t r; asm("cvt.rna.tf32.f32 %0, %1;" : "=r"(r) : "f"(f)); return r;
}
__device__ __forceinline__ float sigf(float x) {
    return __fdividef(1.f, 1.f + __expf(-x));
}
__device__ __forceinline__ void mma_tf32(float* c, const uint32_t* a, const uint32_t* b) {
    asm volatile(
        "mma.sync.aligned.m16n8k8.row.col.f32.tf32.tf32.f32 "
        "{%0,%1,%2,%3}, {%4,%5,%6,%7}, {%8,%9}, {%0,%1,%2,%3};"
        : "+f"(c[0]), "+f"(c[1]), "+f"(c[2]), "+f"(c[3])
        : "r"(a[0]), "r"(a[1]), "r"(a[2]), "r"(a[3]), "r"(b[0]), "r"(b[1]));
}

// SMEM layout (bytes):
//   A: [128][132] u32  @ 0        (67584)
//   W: [96][132]  u32  @ 67584    (50688)
//   bias: 128 f32      @ 118272   (512)
//   D (epilogue overlay on A): [128][100] f32 (51200)
#define SM_W    67584
#define SM_BIAS 118272
#define SM_TOTAL 118784
#define ASTRIDE 132
#define DSTRIDE 100

// ---------------------------------------------------------------------------
// tf32 mma.sync GEMM + fused GRU gating.
// CTA: 128 M x 96 N (3 gates x 32 h). K staged in two 128-halves in SMEM.
// ---------------------------------------------------------------------------
__global__ void __launch_bounds__(256, 1)
gru_mma_kernel(const float* __restrict__ Xin,
               const float* __restrict__ Wg, long long sWs,
               const float* __restrict__ BIg, const float* __restrict__ BHg, int sBs,
               int layer)
{
    extern __shared__ char smem[];
    uint32_t* Asm = (uint32_t*)smem;               // [128][132]
    uint32_t* Wsm = (uint32_t*)(smem + SM_W);      // [96][132]
    float*  sbias = (float*)(smem + SM_BIAS);
    float*  Dsm   = (float*)smem;                  // epilogue overlay [128][100]

    const int tid = threadIdx.x;
    const int wid = tid >> 5;
    const int lane = tid & 31;
    const int lq = lane >> 2;      // 0..7
    const int lr = lane & 3;       // 0..3

    const int s = blockIdx.z;
    const float* A = (layer == 0) ? Xin
                   : (g_h + (size_t)(s * LL + layer - 1) * MTOT * HH);
    float* O = g_h + (size_t)(s * LL + layer) * MTOT * HH;
    const float* W  = Wg  + (size_t)s * sWs;
    const float* BI = BIg + s * sBs;
    const float* BH = BHg + s * sBs;

    const int mBase = blockIdx.x * 128;
    const int hb = blockIdx.y * 32;

    const int wm = (wid & 3) * 32;   // warp M offset
    const int wn = (wid >> 2) * 48;  // warp N offset

    float acc[2][6][4];
#pragma unroll
    for (int mt = 0; mt < 2; mt++)
#pragma unroll
        for (int nt = 0; nt < 6; nt++)
#pragma unroll
            for (int q = 0; q < 4; q++) acc[mt][nt][q] = 0.f;

    // bias (once)
    if (tid < 32)       sbias[tid]  = __ldg(&BI[hb + tid])            + __ldg(&BH[hb + tid]);
    else if (tid < 64)  sbias[tid]  = __ldg(&BI[256 + hb + tid - 32]) + __ldg(&BH[256 + hb + tid - 32]);
    else if (tid < 96)  sbias[tid]  = __ldg(&BI[512 + hb + tid - 64]);
    else if (tid < 128) sbias[tid]  = __ldg(&BH[512 + hb + tid - 96]);

#pragma unroll
    for (int p = 0; p < 2; ++p) {
        if (p) __syncthreads();   // previous compute done before overwriting SMEM

        // load A half: 128 rows x 32 float4
#pragma unroll
        for (int j = 0; j < 16; ++j) {
            const int i = tid + 256 * j;
            const int row = i >> 5;
            const int f4 = i & 31;
            const float4 v = __ldg((const float4*)(A + (size_t)(mBase + row) * KK + p * 128) + f4);
            uint4 t;
            t.x = f2tf(v.x); t.y = f2tf(v.y); t.z = f2tf(v.z); t.w = f2tf(v.w);
            *(uint4*)(Asm + row * ASTRIDE + f4 * 4) = t;
        }
        // load W half: 96 gathered rows x 32 float4
#pragma unroll
        for (int j = 0; j < 12; ++j) {
            const int i = tid + 256 * j;
            const int n = i >> 5;
            const int f4 = i & 31;
            const int grow = (n >> 5) * 256 + hb + (n & 31);
            const float4 v = __ldg((const float4*)(W + (size_t)grow * KK + p * 128) + f4);
            uint4 t;
            t.x = f2tf(v.x); t.y = f2tf(v.y); t.z = f2tf(v.z); t.w = f2tf(v.w);
            *(uint4*)(Wsm + n * ASTRIDE + f4 * 4) = t;
        }
        __syncthreads();

        // compute: 16 k-steps of 8
#pragma unroll
        for (int kk = 0; kk < 16; ++kk) {
            const int kc = kk * 8 + lr;
            uint32_t a[2][4];
#pragma unroll
            for (int mt = 0; mt < 2; mt++) {
                const uint32_t* pa = Asm + (wm + mt * 16 + lq) * ASTRIDE + kc;
                a[mt][0] = pa[0];
                a[mt][1] = pa[8 * ASTRIDE];
                a[mt][2] = pa[4];
                a[mt][3] = pa[8 * ASTRIDE + 4];
            }
            uint32_t b[6][2];
#pragma unroll
            for (int nt = 0; nt < 6; nt++) {
                const uint32_t* pb = Wsm + (wn + nt * 8 + lq) * ASTRIDE + kc;
                b[nt][0] = pb[0];
                b[nt][1] = pb[4];
            }
#pragma unroll
            for (int mt = 0; mt < 2; mt++)
#pragma unroll
                for (int nt = 0; nt < 6; nt++)
                    mma_tf32(acc[mt][nt], a[mt], b[nt]);
        }
    }

    __syncthreads();   // done reading A/W SMEM before D overlay

    // write accumulators to SMEM D [128][100]
#pragma unroll
    for (int mt = 0; mt < 2; mt++) {
#pragma unroll
        for (int nt = 0; nt < 6; nt++) {
            const int row = wm + mt * 16 + lq;
            const int col = wn + nt * 8 + 2 * lr;
            *(float2*)(Dsm + row * DSTRIDE + col) =
                make_float2(acc[mt][nt][0], acc[mt][nt][1]);
            *(float2*)(Dsm + (row + 8) * DSTRIDE + col) =
                make_float2(acc[mt][nt][2], acc[mt][nt][3]);
        }
    }
    __syncthreads();

    // gate + store: 4096 outputs, coalesced
#pragma unroll
    for (int jj = 0; jj < 16; ++jj) {
        const int idx = tid + 256 * jj;
        const int m = idx >> 5;
        const int hl = idx & 31;
        const float gr = Dsm[m * DSTRIDE + hl]      + sbias[hl];
        const float gz = Dsm[m * DSTRIDE + 32 + hl] + sbias[32 + hl];
        const float gn = Dsm[m * DSTRIDE + 64 + hl] + sbias[64 + hl];
        const float r = sigf(gr);
        const float z = sigf(gz);
        const float n = 2.f * sigf(2.f * (gn + r * sbias[96 + hl])) - 1.f;
        O[(size_t)(mBase + m) * HH + hb + hl] = (1.f - z) * n;
    }
}

// ---------------------------------------------------------------------------
// Attention/selection table kernels (unchanged)
// ---------------------------------------------------------------------------
__global__ __launch_bounds__(256)
void table_kernel(const float* __restrict__ hidden,
                  const float* __restrict__ w_lw,
                  const float* __restrict__ b_lw,
                  const float* __restrict__ w_sel)
{
    const int t = blockIdx.x;
    const int s = blockIdx.y;
    const int tid = threadIdx.x;
    const int lane = tid & 31;
    const int wp = tid >> 5;

    __shared__ float ep[512][8];
    __shared__ float red[4][3];

    float wr[7][8];
#pragma unroll
    for (int q = 0; q < 7; q++)
#pragma unroll
        for (int j = 0; j < 8; j++) {
            const int idx = lane + 32 * j;
            wr[q][j] = (q < 4) ? __ldg(&w_lw[q * 256 + idx])
                               : __ldg(&w_sel[(q - 4) * 512 + idx]);
        }

    for (int p = wp; p < 512; p += 8) {
        const int b = p >> 2, l = p & 3;
        const float* hr = g_h + ((size_t)(s * LL + l) * MTOT + (size_t)b * TT + t) * HH;
        float acc[7] = {0, 0, 0, 0, 0, 0, 0};
#pragma unroll
        for (int j = 0; j < 8; j++) {
            const float hv = __ldg(&hr[lane + 32 * j]);
#pragma unroll
            for (int q = 0; q < 7; q++) acc[q] += hv * wr[q][j];
        }
#pragma unroll
        for (int q = 0; q < 7; q++) {
#pragma unroll
            for (int off = 16; off; off >>= 1)
                acc[q] += __shfl_xor_sync(0xffffffffu, acc[q], off);
        }
        if (lane < 7) ep[p][lane] = acc[lane];
    }
    __syncthreads();

    float sc[3] = {0.f, 0.f, 0.f};
    if (tid < 128) {
        const int b = tid;
        float bl[4];
#pragma unroll
        for (int lp = 0; lp < 4; lp++) bl[lp] = __ldg(&b_lw[lp]);
        float attn[4];
#pragma unroll
        for (int l = 0; l < 4; l++) {
            float a = 0.f;
#pragma unroll
            for (int lp = 0; lp < 4; lp++)
                a += __ldg(&hidden[b * 16 + l * 4 + lp]) * (ep[b * 4 + l][lp] + bl[lp]);
            attn[l] = a;
        }
        const float mx = fmaxf(fmaxf(attn[0], attn[1]), fmaxf(attn[2], attn[3]));
        float ee[4], ssum = 0.f;
#pragma unroll
        for (int l = 0; l < 4; l++) { ee[l] = __expf(attn[l] - mx); ssum += ee[l]; }
        const float inv = 1.f / ssum;
#pragma unroll
        for (int l = 0; l < 4; l++) {
            const float a = ee[l] * inv;
#pragma unroll
            for (int q = 0; q < 3; q++) sc[q] += a * ep[b * 4 + l][4 + q];
        }
#pragma unroll
        for (int q = 0; q < 3; q++)
#pragma unroll
            for (int off = 16; off; off >>= 1)
                sc[q] += __shfl_xor_sync(0xffffffffu, sc[q], off);
        if (lane == 0) { red[wp][0] = sc[0]; red[wp][1] = sc[1]; red[wp][2] = sc[2]; }
    }
    __syncthreads();
    if (tid < 3) {
        const float v = red[0][tid] + red[1][tid] + red[2][tid] + red[3][tid];
        g_tabctx[(t * 3 + s) * 3 + tid] = v;
    }
}

__global__ __launch_bounds__(256)
void xproj_kernel(const float* __restrict__ x,
                  const float* __restrict__ w_sel,
                  const float* __restrict__ b_sel)
{
    const int tau = blockIdx.x + 1;
    const int tid = threadIdx.x;
    const int lane = tid & 31, wp = tid >> 5;
    __shared__ float red[3][8];
    float xs = 0.f;
    const float* xp = x + (size_t)tau * II + tid;
#pragma unroll 4
    for (int b = 0; b < 128; b++) xs += __ldg(&xp[(size_t)b * TT * II]);
    float sc[3];
#pragma unroll
    for (int q = 0; q < 3; q++) sc[q] = xs * __ldg(&w_sel[q * 512 + 256 + tid]);
#pragma unroll
    for (int q = 0; q < 3; q++)
#pragma unroll
        for (int off = 16; off; off >>= 1)
            sc[q] += __shfl_xor_sync(0xffffffffu, sc[q], off);
    if (lane == 0) { red[0][wp] = sc[0]; red[1][wp] = sc[1]; red[2][wp] = sc[2]; }
    __syncthreads();
    if (tid < 3) {
        float v = 0.f;
#pragma unroll
        for (int w2 = 0; w2 < 8; w2++) v += red[tid][w2];
        g_xproj[tau * 3 + tid] = v + 128.f * __ldg(&b_sel[tid]);
    }
}

__global__ void serial_kernel()
{
    __shared__ float tab[255 * 9];
    __shared__ float xp[256 * 3];
    const int tid = threadIdx.x;
    for (int i = tid; i < 255 * 9; i += 256) tab[i] = g_tabctx[i];
    for (int i = tid; i < 256 * 3; i += 256) xp[i] = g_xproj[i];
    __syncthreads();
    if (tid == 0) {
        g_cur[0] = 0;
        int cur = 0;
        for (int tau = 1; tau < 256; tau++) {
            const float* tv = &tab[((tau - 1) * 3 + cur) * 3];
            const float v0 = tv[0] + xp[tau * 3 + 0];
            const float v1 = tv[1] + xp[tau * 3 + 1];
            const float v2 = tv[2] + xp[tau * 3 + 2];
            int c = 0; float best = v0;
            if (v1 > best) { best = v1; c = 1; }
            if (v2 > best) { best = v2; c = 2; }
            cur = c; g_cur[tau] = c;
        }
    }
}

__global__ __launch_bounds__(256)
void gather_kernel(float* __restrict__ out, long long n)
{
    const long long idx = (long long)blockIdx.x * 256 + threadIdx.x;
    if (idx >= n) return;
    const long long BTH = (long long)BB * TT * HH;
    int b, t, h;
    if (idx < BTH) {
        b = (int)(idx >> 16);
        const int r = (int)(idx & 65535);
        t = r >> 8; h = r & 255;
    } else {
        const long long j = idx - BTH;
        if (j >= (long long)BB * HH) { out[idx] = 0.f; return; }
        b = (int)(j >> 8); h = (int)(j & 255); t = TT - 1;
    }
    const int cur = g_cur[t];
    out[idx] = g_h[((size_t)(cur * LL + (LL - 1)) * MTOT + (size_t)b * TT + t) * HH + h];
}

// ---------------------------------------------------------------------------
extern "C" void kernel_launch(void* const* d_in, const int* in_sizes, int n_in,
                              void* d_out, int out_size)
{
    (void)in_sizes; (void)n_in;
    const float* x      = (const float*)d_in[0];
    const float* hidden = (const float*)d_in[1];
    const float* w_ih0  = (const float*)d_in[2];
    const float* b_ih0  = (const float*)d_in[3];
    const float* b_hh0  = (const float*)d_in[4];
    const float* w_ih   = (const float*)d_in[5];
    const float* b_ih   = (const float*)d_in[6];
    const float* b_hh   = (const float*)d_in[7];
    const float* w_lw   = (const float*)d_in[8];
    const float* b_lw   = (const float*)d_in[9];
    const float* w_sel  = (const float*)d_in[10];
    const float* b_sel  = (const float*)d_in[11];
    float* out = (float*)d_out;

    cudaFuncSetAttribute(gru_mma_kernel,
                         cudaFuncAttributeMaxDynamicSharedMemorySize, SM_TOTAL);

    const dim3 gGemm(MTOT / 128, HH / 32, SS);

    gru_mma_kernel<<<gGemm, 256, SM_TOTAL>>>(x, w_ih0, (long long)768 * 256,
                                             b_ih0, b_hh0, 768, 0);
    for (int l = 1; l < LL; l++) {
        gru_mma_kernel<<<gGemm, 256, SM_TOTAL>>>(
            x,
            w_ih + (size_t)(l - 1) * 768 * 256, (long long)(LL - 1) * 768 * 256,
            b_ih + (size_t)(l - 1) * 768,
            b_hh + (size_t)(l - 1) * 768, (LL - 1) * 768,
            l);
    }

    xproj_kernel<<<255, 256>>>(x, w_sel, b_sel);
    table_kernel<<<dim3(255, 3), 256>>>(hidden, w_lw, b_lw, w_sel);
    serial_kernel<<<1, 256>>>();

    const long long n = (long long)out_size;
    const int nb = (int)((n + 255) / 256);
    gather_kernel<<<nb, 256>>>(out, n);
}

// round 4
// speedup vs baseline: 2.4978x; 1.1182x over previous
#include <cuda_runtime.h>
#include <cstdint>

// Problem constants
#define BB 128
#define TT 256
#define II 256
#define HH 256
#define LL 4
#define SS 3
#define KK 256
#define MTOT (BB*TT)

// Scratch
__device__ float g_h[(size_t)SS * LL * MTOT * HH];   // h_all[s][l][m][h]
__device__ float g_tabctx[255 * 3 * 3];
__device__ float g_xproj[256 * 3];
__device__ int   g_cur[256];

__device__ __forceinline__ float sigf(float x) {
    return __fdividef(1.f, 1.f + __expf(-x));
}
__device__ __forceinline__ uint32_t smem_u32(const void* p) {
    uint32_t a;
    asm("{ .reg .u64 t; cvta.to.shared.u64 t, %1; cvt.u32.u64 %0, t; }" : "=r"(a) : "l"(p));
    return a;
}
__device__ __forceinline__ void mma_tf32(float* c, const uint32_t* a, const uint32_t* b) {
    asm volatile(
        "mma.sync.aligned.m16n8k8.row.col.f32.tf32.tf32.f32 "
        "{%0,%1,%2,%3}, {%4,%5,%6,%7}, {%8,%9}, {%0,%1,%2,%3};"
        : "+f"(c[0]), "+f"(c[1]), "+f"(c[2]), "+f"(c[3])
        : "r"(a[0]), "r"(a[1]), "r"(a[2]), "r"(a[3]), "r"(b[0]), "r"(b[1]));
}
#define CP16(dst, src) \
    asm volatile("cp.async.cg.shared.global [%0], [%1], 16;" :: "r"(dst), "l"(src))
#define CP_COMMIT() asm volatile("cp.async.commit_group;" ::: "memory")
#define CP_WAIT1()  asm volatile("cp.async.wait_group 1;" ::: "memory")

// SMEM: 3 stages x (A[256][36] + W[96][36]) fp32 + bias(128 f4)
//   stage bytes = (256*36 + 96*36)*4 = 50688
//   epilogue D overlay [256][100] f32 = 102400 (fits in stages 0..2)
#define STAGE_FLOATS 12672
#define STAGE_BYTES  50688
#define A_FLOATS     9216
#define SM_BIAS      (3 * STAGE_BYTES)          // 152064
#define SM_TOTAL     (SM_BIAS + 512)            // 152576
#define KSTRIDE 36
#define DSTRIDE 100

// ---------------------------------------------------------------------------
// tf32 mma.sync GEMM + fused GRU gating.
// CTA: 256 M x 96 N (3 gates x 32 h). 8 warps (4m x 2n), warp tile 64x48.
// K pipelined in 8 chunks of 32 via cp.async, 3-stage.
// ---------------------------------------------------------------------------
__global__ void __launch_bounds__(256, 1)
gru_mma_kernel(const float* __restrict__ Xin,
               const float* __restrict__ Wg, long long sWs,
               const float* __restrict__ BIg, const float* __restrict__ BHg, int sBs,
               int layer)
{
    extern __shared__ char smem[];
    const uint32_t sbase = smem_u32(smem);
    float* sbias = (float*)(smem + SM_BIAS);
    float* Dsm   = (float*)smem;

    const int tid = threadIdx.x;
    const int wid = tid >> 5;
    const int lane = tid & 31;
    const int lq = lane >> 2;
    const int lr = lane & 3;

    const int s = blockIdx.z;
    const float* A = (layer == 0) ? Xin
                   : (g_h + (size_t)(s * LL + layer - 1) * MTOT * HH);
    float* O = g_h + (size_t)(s * LL + layer) * MTOT * HH;
    const float* W  = Wg  + (size_t)s * sWs;
    const float* BI = BIg + s * sBs;
    const float* BH = BHg + s * sBs;

    const int mBase = blockIdx.x * 256;
    const int hb = blockIdx.y * 32;

    const int wm = (wid & 3) * 64;   // warp M offset (4 warps over 256 rows)
    const int wn = (wid >> 2) * 48;  // warp N offset (2 warps over 96 cols)

    // bias (r: BI+BH, z: BI+BH, n: BI, n-hidden: BH)
    if (tid < 32)       sbias[tid] = __ldg(&BI[hb + tid])            + __ldg(&BH[hb + tid]);
    else if (tid < 64)  sbias[tid] = __ldg(&BI[256 + hb + tid - 32]) + __ldg(&BH[256 + hb + tid - 32]);
    else if (tid < 96)  sbias[tid] = __ldg(&BI[512 + hb + tid - 64]);
    else if (tid < 128) sbias[tid] = __ldg(&BH[512 + hb + tid - 96]);

    float acc[4][6][4];
#pragma unroll
    for (int mt = 0; mt < 4; mt++)
#pragma unroll
        for (int nt = 0; nt < 6; nt++)
#pragma unroll
            for (int q = 0; q < 4; q++) acc[mt][nt][q] = 0.f;

    // ---- stage loader (A: 256 rows x 128B, W: 96 gathered rows x 128B) ----
    const int arow = tid >> 3;          // 0..31 step base for A (x8 = 256)
    const int seg  = tid & 7;           // 16B segment within 128B row chunk
    auto load_stage = [&](int buf, int k0) {
        const uint32_t dstA = sbase + buf * STAGE_BYTES + (arow * KSTRIDE + seg * 4) * 4;
        const float* srcA = A + (size_t)(mBase + arow) * KK + k0 + seg * 4;
#pragma unroll
        for (int j = 0; j < 8; ++j)
            CP16(dstA + j * 32 * KSTRIDE * 4, srcA + (size_t)32 * j * KK);
#pragma unroll
        for (int j = 0; j < 3; ++j) {
            const int n = arow + 32 * j;                     // 0..95
            const int grow = (n >> 5) * 256 + hb + (n & 31); // gate-gathered W row
            const uint32_t dstW = sbase + buf * STAGE_BYTES
                                + (A_FLOATS + n * KSTRIDE + seg * 4) * 4;
            CP16(dstW, W + (size_t)grow * KK + k0 + seg * 4);
        }
    };

    load_stage(0, 0);  CP_COMMIT();
    load_stage(1, 32); CP_COMMIT();

#pragma unroll 1
    for (int st = 0; st < 8; ++st) {
        CP_WAIT1();
        __syncthreads();

        const int buf = st % 3;
        const uint32_t* As = (const uint32_t*)(smem + buf * STAGE_BYTES);
        const uint32_t* Ws = As + A_FLOATS;

#pragma unroll
        for (int kk = 0; kk < 4; ++kk) {
            const int kc = kk * 8 + lr;
            uint32_t a[4][4];
#pragma unroll
            for (int mt = 0; mt < 4; mt++) {
                const uint32_t* pa = As + (wm + mt * 16 + lq) * KSTRIDE + kc;
                a[mt][0] = pa[0];
                a[mt][1] = pa[8 * KSTRIDE];
                a[mt][2] = pa[4];
                a[mt][3] = pa[8 * KSTRIDE + 4];
            }
            uint32_t b[6][2];
#pragma unroll
            for (int nt = 0; nt < 6; nt++) {
                const uint32_t* pb = Ws + (wn + nt * 8 + lq) * KSTRIDE + kc;
                b[nt][0] = pb[0];
                b[nt][1] = pb[4];
            }
#pragma unroll
            for (int mt = 0; mt < 4; mt++)
#pragma unroll
                for (int nt = 0; nt < 6; nt++)
                    mma_tf32(acc[mt][nt], a[mt], b[nt]);
        }

        if (st + 2 < 8) load_stage((st + 2) % 3, (st + 2) * 32);
        CP_COMMIT();
    }

    __syncthreads();   // pipeline done; overlay D on stage buffers

    // accumulators -> SMEM D [256][100]
#pragma unroll
    for (int mt = 0; mt < 4; mt++) {
#pragma unroll
        for (int nt = 0; nt < 6; nt++) {
            const int row = wm + mt * 16 + lq;
            const int col = wn + nt * 8 + 2 * lr;
            *(float2*)(Dsm + row * DSTRIDE + col) =
                make_float2(acc[mt][nt][0], acc[mt][nt][1]);
            *(float2*)(Dsm + (row + 8) * DSTRIDE + col) =
                make_float2(acc[mt][nt][2], acc[mt][nt][3]);
        }
    }
    __syncthreads();

    // gate + coalesced store: 256 rows x 32 h
#pragma unroll
    for (int jj = 0; jj < 32; ++jj) {
        const int idx = tid + 256 * jj;
        const int m = idx >> 5;
        const int hl = idx & 31;
        const float gr = Dsm[m * DSTRIDE + hl]      + sbias[hl];
        const float gz = Dsm[m * DSTRIDE + 32 + hl] + sbias[32 + hl];
        const float gn = Dsm[m * DSTRIDE + 64 + hl] + sbias[64 + hl];
        const float r = sigf(gr);
        const float z = sigf(gz);
        const float n = 2.f * sigf(2.f * (gn + r * sbias[96 + hl])) - 1.f;
        O[(size_t)(mBase + m) * HH + hb + hl] = (1.f - z) * n;
    }
}

// ---------------------------------------------------------------------------
// Attention/selection table kernels (unchanged)
// ---------------------------------------------------------------------------
__global__ __launch_bounds__(256)
void table_kernel(const float* __restrict__ hidden,
                  const float* __restrict__ w_lw,
                  const float* __restrict__ b_lw,
                  const float* __restrict__ w_sel)
{
    const int t = blockIdx.x;
    const int s = blockIdx.y;
    const int tid = threadIdx.x;
    const int lane = tid & 31;
    const int wp = tid >> 5;

    __shared__ float ep[512][8];
    __shared__ float red[4][3];

    float wr[7][8];
#pragma unroll
    for (int q = 0; q < 7; q++)
#pragma unroll
        for (int j = 0; j < 8; j++) {
            const int idx = lane + 32 * j;
            wr[q][j] = (q < 4) ? __ldg(&w_lw[q * 256 + idx])
                               : __ldg(&w_sel[(q - 4) * 512 + idx]);
        }

    for (int p = wp; p < 512; p += 8) {
        const int b = p >> 2, l = p & 3;
        const float* hr = g_h + ((size_t)(s * LL + l) * MTOT + (size_t)b * TT + t) * HH;
        float acc[7] = {0, 0, 0, 0, 0, 0, 0};
#pragma unroll
        for (int j = 0; j < 8; j++) {
            const float hv = __ldg(&hr[lane + 32 * j]);
#pragma unroll
            for (int q = 0; q < 7; q++) acc[q] += hv * wr[q][j];
        }
#pragma unroll
        for (int q = 0; q < 7; q++) {
#pragma unroll
            for (int off = 16; off; off >>= 1)
                acc[q] += __shfl_xor_sync(0xffffffffu, acc[q], off);
        }
        if (lane < 7) ep[p][lane] = acc[lane];
    }
    __syncthreads();

    float sc[3] = {0.f, 0.f, 0.f};
    if (tid < 128) {
        const int b = tid;
        float bl[4];
#pragma unroll
        for (int lp = 0; lp < 4; lp++) bl[lp] = __ldg(&b_lw[lp]);
        float attn[4];
#pragma unroll
        for (int l = 0; l < 4; l++) {
            float a = 0.f;
#pragma unroll
            for (int lp = 0; lp < 4; lp++)
                a += __ldg(&hidden[b * 16 + l * 4 + lp]) * (ep[b * 4 + l][lp] + bl[lp]);
            attn[l] = a;
        }
        const float mx = fmaxf(fmaxf(attn[0], attn[1]), fmaxf(attn[2], attn[3]));
        float ee[4], ssum = 0.f;
#pragma unroll
        for (int l = 0; l < 4; l++) { ee[l] = __expf(attn[l] - mx); ssum += ee[l]; }
        const float inv = 1.f / ssum;
#pragma unroll
        for (int l = 0; l < 4; l++) {
            const float a = ee[l] * inv;
#pragma unroll
            for (int q = 0; q < 3; q++) sc[q] += a * ep[b * 4 + l][4 + q];
        }
#pragma unroll
        for (int q = 0; q < 3; q++)
#pragma unroll
            for (int off = 16; off; off >>= 1)
                sc[q] += __shfl_xor_sync(0xffffffffu, sc[q], off);
        if (lane == 0) { red[wp][0] = sc[0]; red[wp][1] = sc[1]; red[wp][2] = sc[2]; }
    }
    __syncthreads();
    if (tid < 3) {
        const float v = red[0][tid] + red[1][tid] + red[2][tid] + red[3][tid];
        g_tabctx[(t * 3 + s) * 3 + tid] = v;
    }
}

__global__ __launch_bounds__(256)
void xproj_kernel(const float* __restrict__ x,
                  const float* __restrict__ w_sel,
                  const float* __restrict__ b_sel)
{
    const int tau = blockIdx.x + 1;
    const int tid = threadIdx.x;
    const int lane = tid & 31, wp = tid >> 5;
    __shared__ float red[3][8];
    float xs = 0.f;
    const float* xp = x + (size_t)tau * II + tid;
#pragma unroll 4
    for (int b = 0; b < 128; b++) xs += __ldg(&xp[(size_t)b * TT * II]);
    float sc[3];
#pragma unroll
    for (int q = 0; q < 3; q++) sc[q] = xs * __ldg(&w_sel[q * 512 + 256 + tid]);
#pragma unroll
    for (int q = 0; q < 3; q++)
#pragma unroll
        for (int off = 16; off; off >>= 1)
            sc[q] += __shfl_xor_sync(0xffffffffu, sc[q], off);
    if (lane == 0) { red[0][wp] = sc[0]; red[1][wp] = sc[1]; red[2][wp] = sc[2]; }
    __syncthreads();
    if (tid < 3) {
        float v = 0.f;
#pragma unroll
        for (int w2 = 0; w2 < 8; w2++) v += red[tid][w2];
        g_xproj[tau * 3 + tid] = v + 128.f * __ldg(&b_sel[tid]);
    }
}

__global__ void serial_kernel()
{
    __shared__ float tab[255 * 9];
    __shared__ float xp[256 * 3];
    const int tid = threadIdx.x;
    for (int i = tid; i < 255 * 9; i += 256) tab[i] = g_tabctx[i];
    for (int i = tid; i < 256 * 3; i += 256) xp[i] = g_xproj[i];
    __syncthreads();
    if (tid == 0) {
        g_cur[0] = 0;
        int cur = 0;
        for (int tau = 1; tau < 256; tau++) {
            const float* tv = &tab[((tau - 1) * 3 + cur) * 3];
            const float v0 = tv[0] + xp[tau * 3 + 0];
            const float v1 = tv[1] + xp[tau * 3 + 1];
            const float v2 = tv[2] + xp[tau * 3 + 2];
            int c = 0; float best = v0;
            if (v1 > best) { best = v1; c = 1; }
            if (v2 > best) { best = v2; c = 2; }
            cur = c; g_cur[tau] = c;
        }
    }
}

__global__ __launch_bounds__(256)
void gather_kernel(float* __restrict__ out, long long n)
{
    const long long idx = (long long)blockIdx.x * 256 + threadIdx.x;
    if (idx >= n) return;
    const long long BTH = (long long)BB * TT * HH;
    int b, t, h;
    if (idx < BTH) {
        b = (int)(idx >> 16);
        const int r = (int)(idx & 65535);
        t = r >> 8; h = r & 255;
    } else {
        const long long j = idx - BTH;
        if (j >= (long long)BB * HH) { out[idx] = 0.f; return; }
        b = (int)(j >> 8); h = (int)(j & 255); t = TT - 1;
    }
    const int cur = g_cur[t];
    out[idx] = g_h[((size_t)(cur * LL + (LL - 1)) * MTOT + (size_t)b * TT + t) * HH + h];
}

// ---------------------------------------------------------------------------
extern "C" void kernel_launch(void* const* d_in, const int* in_sizes, int n_in,
                              void* d_out, int out_size)
{
    (void)in_sizes; (void)n_in;
    const float* x      = (const float*)d_in[0];
    const float* hidden = (const float*)d_in[1];
    const float* w_ih0  = (const float*)d_in[2];
    const float* b_ih0  = (const float*)d_in[3];
    const float* b_hh0  = (const float*)d_in[4];
    const float* w_ih   = (const float*)d_in[5];
    const float* b_ih   = (const float*)d_in[6];
    const float* b_hh   = (const float*)d_in[7];
    const float* w_lw   = (const float*)d_in[8];
    const float* b_lw   = (const float*)d_in[9];
    const float* w_sel  = (const float*)d_in[10];
    const float* b_sel  = (const float*)d_in[11];
    float* out = (float*)d_out;

    cudaFuncSetAttribute(gru_mma_kernel,
                         cudaFuncAttributeMaxDynamicSharedMemorySize, SM_TOTAL);

    const dim3 gGemm(MTOT / 256, HH / 32, SS);

    gru_mma_kernel<<<gGemm, 256, SM_TOTAL>>>(x, w_ih0, (long long)768 * 256,
                                             b_ih0, b_hh0, 768, 0);
    for (int l = 1; l < LL; l++) {
        gru_mma_kernel<<<gGemm, 256, SM_TOTAL>>>(
            x,
            w_ih + (size_t)(l - 1) * 768 * 256, (long long)(LL - 1) * 768 * 256,
            b_ih + (size_t)(l - 1) * 768,
            b_hh + (size_t)(l - 1) * 768, (LL - 1) * 768,
            l);
    }

    xproj_kernel<<<255, 256>>>(x, w_sel, b_sel);
    table_kernel<<<dim3(255, 3), 256>>>(hidden, w_lw, b_lw, w_sel);
    serial_kernel<<<1, 256>>>();

    const long long n = (long long)out_size;
    const int nb = (int)((n + 255) / 256);
    gather_kernel<<<nb, 256>>>(out, n);
}

// round 5
// speedup vs baseline: 3.8183x; 1.5287x over previous
#include <cuda_runtime.h>
#include <cuda_fp16.h>
#include <cstdint>

// Problem constants
#define BB 128
#define TT 256
#define II 256
#define HH 256
#define LL 4
#define SS 3
#define KK 256
#define MTOT (BB*TT)

// Scratch
__device__ float  g_h [(size_t)SS * LL * MTOT * HH];  // fp32 h (outputs/gather)
__device__ __half g_hh[(size_t)SS * LL * MTOT * HH];  // fp16 h (GEMM A / table)
__device__ __half g_xh[(size_t)MTOT * II];            // fp16 x
__device__ __half g_w0h[(size_t)SS * 768 * 256];      // fp16 w_ih0
__device__ __half g_wh [(size_t)SS * 3 * 768 * 256];  // fp16 w_ih
__device__ float g_tabctx[255 * 3 * 3];
__device__ float g_xproj[256 * 3];
__device__ int   g_cur[256];

__device__ __forceinline__ float sigf(float x) {
    return __fdividef(1.f, 1.f + __expf(-x));
}
__device__ __forceinline__ uint32_t smem_u32(const void* p) {
    uint32_t a;
    asm("{ .reg .u64 t; cvta.to.shared.u64 t, %1; cvt.u32.u64 %0, t; }" : "=r"(a) : "l"(p));
    return a;
}
__device__ __forceinline__ void mma_f16(float* c, const uint32_t* a, const uint32_t* b) {
    asm volatile(
        "mma.sync.aligned.m16n8k16.row.col.f32.f16.f16.f32 "
        "{%0,%1,%2,%3}, {%4,%5,%6,%7}, {%8,%9}, {%0,%1,%2,%3};"
        : "+f"(c[0]), "+f"(c[1]), "+f"(c[2]), "+f"(c[3])
        : "r"(a[0]), "r"(a[1]), "r"(a[2]), "r"(a[3]), "r"(b[0]), "r"(b[1]));
}
#define LDSM4(r0, r1, r2, r3, addr) \
    asm volatile("ldmatrix.sync.aligned.m8n8.x4.shared.b16 {%0,%1,%2,%3}, [%4];" \
        : "=r"(r0), "=r"(r1), "=r"(r2), "=r"(r3) : "r"(addr))
#define CP16(dst, src) \
    asm volatile("cp.async.cg.shared.global [%0], [%1], 16;" :: "r"(dst), "l"(src))
#define CP_COMMIT() asm volatile("cp.async.commit_group;" ::: "memory")
#define CP_WAIT1()  asm volatile("cp.async.wait_group 1;" ::: "memory")

// SMEM: 3 stages x (A[256][64]h + W[96][64]h) + bias
//   stage = 256*128 + 96*128 = 45056 B; 3 stages = 135168; bias @ 135168
#define STAGE_BYTES 45056
#define W_OFF       32768
#define SM_BIAS     135168
#define SM_TOTAL    135680
#define DSTRIDE 100

// ---------------------------------------------------------------------------
// fp16 mma.sync GEMM + fused GRU gating.
// CTA: 256 M x 96 N (3 gates x 32 h). 8 warps (4m x 2n), warp tile 64x48.
// K pipelined in 4 chunks of 64 via cp.async (3-stage); XOR-swizzled SMEM;
// ldmatrix.x4 fragments.
// ---------------------------------------------------------------------------
__global__ void __launch_bounds__(256, 1)
gru_mma_kernel(const __half* __restrict__ Ag, long long sAs,
               const __half* __restrict__ Wg, long long sWs,
               const float* __restrict__ BIg, const float* __restrict__ BHg, int sBs,
               float* __restrict__ Og, __half* __restrict__ Ohg)
{
    extern __shared__ char smem[];
    const uint32_t sbase = smem_u32(smem);
    float* sbias = (float*)(smem + SM_BIAS);
    float* Dsm   = (float*)smem;

    const int tid = threadIdx.x;
    const int wid = tid >> 5;
    const int lane = tid & 31;
    const int lq = lane >> 2;
    const int lr = lane & 3;

    const int s = blockIdx.z;
    const __half* A = Ag + (size_t)s * sAs;
    const __half* W = Wg + (size_t)s * sWs;
    const float* BI = BIg + s * sBs;
    const float* BH = BHg + s * sBs;
    float*  O  = Og  + (size_t)s * ((size_t)LL * MTOT * HH);
    __half* Oh = Ohg + (size_t)s * ((size_t)LL * MTOT * HH);

    const int mBase = blockIdx.x * 256;
    const int hb = blockIdx.y * 32;

    const int wm = (wid & 3) * 64;   // warp M offset
    const int wn = (wid >> 2) * 48;  // warp N offset

    // bias
    if (tid < 32)       sbias[tid] = __ldg(&BI[hb + tid])            + __ldg(&BH[hb + tid]);
    else if (tid < 64)  sbias[tid] = __ldg(&BI[256 + hb + tid - 32]) + __ldg(&BH[256 + hb + tid - 32]);
    else if (tid < 96)  sbias[tid] = __ldg(&BI[512 + hb + tid - 64]);
    else if (tid < 128) sbias[tid] = __ldg(&BH[512 + hb + tid - 96]);

    float acc[4][6][4];
#pragma unroll
    for (int mt = 0; mt < 4; mt++)
#pragma unroll
        for (int nt = 0; nt < 6; nt++)
#pragma unroll
            for (int q = 0; q < 4; q++) acc[mt][nt][q] = 0.f;

    // ---- stage loader: rows of 64 halves (128 B = 8 x 16B segs), XOR swizzle ----
    const int arow = tid >> 3;   // 0..31
    const int seg  = tid & 7;    // 16B segment id
    auto load_stage = [&](int buf, int k0) {
        const uint32_t stA = sbase + buf * STAGE_BYTES;
#pragma unroll
        for (int j = 0; j < 8; ++j) {
            const int row = arow + 32 * j;
            const uint32_t dst = stA + row * 128 + ((seg ^ (row & 7)) * 16);
            CP16(dst, A + (size_t)(mBase + row) * KK + k0 + seg * 8);
        }
#pragma unroll
        for (int j = 0; j < 3; ++j) {
            const int n = arow + 32 * j;                     // 0..95
            const int grow = (n >> 5) * 256 + hb + (n & 31); // gate-gathered W row
            const uint32_t dst = stA + W_OFF + n * 128 + ((seg ^ (n & 7)) * 16);
            CP16(dst, W + (size_t)grow * KK + k0 + seg * 8);
        }
    };

    // fragment addressing (per-lane constants)
    const int rA_lo = lane & 15;       // row offset within m16 tile
    const int sA    = lane >> 4;       // 0/1: k-seg select
    const int rB_lo = ((lane >> 4) << 3) + (lane & 7);  // n offset within n16 pair
    const int sB    = (lane >> 3) & 1;

    load_stage(0, 0);   CP_COMMIT();
    load_stage(1, 64);  CP_COMMIT();

#pragma unroll 1
    for (int st = 0; st < 4; ++st) {
        CP_WAIT1();
        __syncthreads();

        const int buf = st % 3;
        const uint32_t stA = sbase + buf * STAGE_BYTES;
        const uint32_t stW = stA + W_OFF;

#pragma unroll
        for (int kk = 0; kk < 4; ++kk) {
            uint32_t a[4][4];
#pragma unroll
            for (int mt = 0; mt < 4; mt++) {
                const int row = wm + mt * 16 + rA_lo;
                const uint32_t addr = stA + row * 128
                                    + (((kk * 2 + sA) ^ (row & 7)) * 16);
                LDSM4(a[mt][0], a[mt][1], a[mt][2], a[mt][3], addr);
            }
            uint32_t b[6][2];
#pragma unroll
            for (int np = 0; np < 3; np++) {
                const int n = wn + np * 16 + rB_lo;
                const uint32_t addr = stW + n * 128
                                    + (((kk * 2 + sB) ^ (n & 7)) * 16);
                uint32_t r0, r1, r2, r3;
                LDSM4(r0, r1, r2, r3, addr);
                b[2 * np][0] = r0; b[2 * np][1] = r1;
                b[2 * np + 1][0] = r2; b[2 * np + 1][1] = r3;
            }
#pragma unroll
            for (int mt = 0; mt < 4; mt++)
#pragma unroll
                for (int nt = 0; nt < 6; nt++)
                    mma_f16(acc[mt][nt], a[mt], b[nt]);
        }

        if (st + 2 < 4) load_stage((st + 2) % 3, (st + 2) * 64);
        CP_COMMIT();
    }

    __syncthreads();   // pipeline done; overlay D on stage buffers

    // accumulators -> SMEM D [256][100]
#pragma unroll
    for (int mt = 0; mt < 4; mt++) {
#pragma unroll
        for (int nt = 0; nt < 6; nt++) {
            const int row = wm + mt * 16 + lq;
            const int col = wn + nt * 8 + 2 * lr;
            *(float2*)(Dsm + row * DSTRIDE + col) =
                make_float2(acc[mt][nt][0], acc[mt][nt][1]);
            *(float2*)(Dsm + (row + 8) * DSTRIDE + col) =
                make_float2(acc[mt][nt][2], acc[mt][nt][3]);
        }
    }
    __syncthreads();

    // gate + coalesced dual store (fp32 + fp16-rna)
#pragma unroll
    for (int jj = 0; jj < 32; ++jj) {
        const int idx = tid + 256 * jj;
        const int m = idx >> 5;
        const int hl = idx & 31;
        const float gr = Dsm[m * DSTRIDE + hl]      + sbias[hl];
        const float gz = Dsm[m * DSTRIDE + 32 + hl] + sbias[32 + hl];
        const float gn = Dsm[m * DSTRIDE + 64 + hl] + sbias[64 + hl];
        const float r = sigf(gr);
        const float z = sigf(gz);
        const float n = 2.f * sigf(2.f * (gn + r * sbias[96 + hl])) - 1.f;
        const float hv = (1.f - z) * n;
        O [(size_t)(mBase + m) * HH + hb + hl] = hv;
        Oh[(size_t)(mBase + m) * HH + hb + hl] = __float2half_rn(hv);
    }
}

// ---------------------------------------------------------------------------
// fp32 -> fp16 (rna) conversion, vectorized x4
// ---------------------------------------------------------------------------
__global__ __launch_bounds__(256)
void f2h_kernel(const float* __restrict__ src, __half* __restrict__ dst, int n4)
{
    const int i = blockIdx.x * 256 + threadIdx.x;
    if (i < n4) {
        const float4 v = __ldg((const float4*)src + i);
        __half2* d = (__half2*)dst + 2 * i;
        d[0] = __floats2half2_rn(v.x, v.y);
        d[1] = __floats2half2_rn(v.z, v.w);
    }
}

// ---------------------------------------------------------------------------
// Attention/selection table (reads fp16 h copy)
// ---------------------------------------------------------------------------
__global__ __launch_bounds__(256)
void table_kernel(const float* __restrict__ hidden,
                  const float* __restrict__ w_lw,
                  const float* __restrict__ b_lw,
                  const float* __restrict__ w_sel)
{
    const int t = blockIdx.x;
    const int s = blockIdx.y;
    const int tid = threadIdx.x;
    const int lane = tid & 31;
    const int wp = tid >> 5;

    __shared__ float ep[512][8];
    __shared__ float red[4][3];

    float wr[7][8];
#pragma unroll
    for (int q = 0; q < 7; q++)
#pragma unroll
        for (int j = 0; j < 8; j++) {
            const int idx = lane + 32 * j;
            wr[q][j] = (q < 4) ? __ldg(&w_lw[q * 256 + idx])
                               : __ldg(&w_sel[(q - 4) * 512 + idx]);
        }

    for (int p = wp; p < 512; p += 8) {
        const int b = p >> 2, l = p & 3;
        const __half* hr = g_hh + ((size_t)(s * LL + l) * MTOT + (size_t)b * TT + t) * HH;
        float acc[7] = {0, 0, 0, 0, 0, 0, 0};
#pragma unroll
        for (int j = 0; j < 8; j++) {
            const float hv = __half2float(__ldg(&hr[lane + 32 * j]));
#pragma unroll
            for (int q = 0; q < 7; q++) acc[q] += hv * wr[q][j];
        }
#pragma unroll
        for (int q = 0; q < 7; q++) {
#pragma unroll
            for (int off = 16; off; off >>= 1)
                acc[q] += __shfl_xor_sync(0xffffffffu, acc[q], off);
        }
        if (lane < 7) ep[p][lane] = acc[lane];
    }
    __syncthreads();

    float sc[3] = {0.f, 0.f, 0.f};
    if (tid < 128) {
        const int b = tid;
        float bl[4];
#pragma unroll
        for (int lp = 0; lp < 4; lp++) bl[lp] = __ldg(&b_lw[lp]);
        float attn[4];
#pragma unroll
        for (int l = 0; l < 4; l++) {
            float a = 0.f;
#pragma unroll
            for (int lp = 0; lp < 4; lp++)
                a += __ldg(&hidden[b * 16 + l * 4 + lp]) * (ep[b * 4 + l][lp] + bl[lp]);
            attn[l] = a;
        }
        const float mx = fmaxf(fmaxf(attn[0], attn[1]), fmaxf(attn[2], attn[3]));
        float ee[4], ssum = 0.f;
#pragma unroll
        for (int l = 0; l < 4; l++) { ee[l] = __expf(attn[l] - mx); ssum += ee[l]; }
        const float inv = 1.f / ssum;
#pragma unroll
        for (int l = 0; l < 4; l++) {
            const float a = ee[l] * inv;
#pragma unroll
            for (int q = 0; q < 3; q++) sc[q] += a * ep[b * 4 + l][4 + q];
        }
#pragma unroll
        for (int q = 0; q < 3; q++)
#pragma unroll
            for (int off = 16; off; off >>= 1)
                sc[q] += __shfl_xor_sync(0xffffffffu, sc[q], off);
        if (lane == 0) { red[wp][0] = sc[0]; red[wp][1] = sc[1]; red[wp][2] = sc[2]; }
    }
    __syncthreads();
    if (tid < 3) {
        const float v = red[0][tid] + red[1][tid] + red[2][tid] + red[3][tid];
        g_tabctx[(t * 3 + s) * 3 + tid] = v;
    }
}

__global__ __launch_bounds__(256)
void xproj_kernel(const float* __restrict__ x,
                  const float* __restrict__ w_sel,
                  const float* __restrict__ b_sel)
{
    const int tau = blockIdx.x + 1;
    const int tid = threadIdx.x;
    const int lane = tid & 31, wp = tid >> 5;
    __shared__ float red[3][8];
    float xs = 0.f;
    const float* xp = x + (size_t)tau * II + tid;
#pragma unroll 4
    for (int b = 0; b < 128; b++) xs += __ldg(&xp[(size_t)b * TT * II]);
    float sc[3];
#pragma unroll
    for (int q = 0; q < 3; q++) sc[q] = xs * __ldg(&w_sel[q * 512 + 256 + tid]);
#pragma unroll
    for (int q = 0; q < 3; q++)
#pragma unroll
        for (int off = 16; off; off >>= 1)
            sc[q] += __shfl_xor_sync(0xffffffffu, sc[q], off);
    if (lane == 0) { red[0][wp] = sc[0]; red[1][wp] = sc[1]; red[2][wp] = sc[2]; }
    __syncthreads();
    if (tid < 3) {
        float v = 0.f;
#pragma unroll
        for (int w2 = 0; w2 < 8; w2++) v += red[tid][w2];
        g_xproj[tau * 3 + tid] = v + 128.f * __ldg(&b_sel[tid]);
    }
}

__global__ void serial_kernel()
{
    __shared__ float tab[255 * 9];
    __shared__ float xp[256 * 3];
    const int tid = threadIdx.x;
    for (int i = tid; i < 255 * 9; i += 256) tab[i] = g_tabctx[i];
    for (int i = tid; i < 256 * 3; i += 256) xp[i] = g_xproj[i];
    __syncthreads();
    if (tid == 0) {
        g_cur[0] = 0;
        int cur = 0;
        for (int tau = 1; tau < 256; tau++) {
            const float* tv = &tab[((tau - 1) * 3 + cur) * 3];
            const float v0 = tv[0] + xp[tau * 3 + 0];
            const float v1 = tv[1] + xp[tau * 3 + 1];
            const float v2 = tv[2] + xp[tau * 3 + 2];
            int c = 0; float best = v0;
            if (v1 > best) { best = v1; c = 1; }
            if (v2 > best) { best = v2; c = 2; }
            cur = c; g_cur[tau] = c;
        }
    }
}

__global__ __launch_bounds__(256)
void gather_kernel(float* __restrict__ out, long long n)
{
    const long long idx = (long long)blockIdx.x * 256 + threadIdx.x;
    if (idx >= n) return;
    const long long BTH = (long long)BB * TT * HH;
    int b, t, h;
    if (idx < BTH) {
        b = (int)(idx >> 16);
        const int r = (int)(idx & 65535);
        t = r >> 8; h = r & 255;
    } else {
        const long long j = idx - BTH;
        if (j >= (long long)BB * HH) { out[idx] = 0.f; return; }
        b = (int)(j >> 8); h = (int)(j & 255); t = TT - 1;
    }
    const int cur = g_cur[t];
    out[idx] = g_h[((size_t)(cur * LL + (LL - 1)) * MTOT + (size_t)b * TT + t) * HH + h];
}

// ---------------------------------------------------------------------------
extern "C" void kernel_launch(void* const* d_in, const int* in_sizes, int n_in,
                              void* d_out, int out_size)
{
    (void)in_sizes; (void)n_in;
    const float* x      = (const float*)d_in[0];
    const float* hidden = (const float*)d_in[1];
    const float* w_ih0  = (const float*)d_in[2];
    const float* b_ih0  = (const float*)d_in[3];
    const float* b_hh0  = (const float*)d_in[4];
    const float* w_ih   = (const float*)d_in[5];
    const float* b_ih   = (const float*)d_in[6];
    const float* b_hh   = (const float*)d_in[7];
    const float* w_lw   = (const float*)d_in[8];
    const float* b_lw   = (const float*)d_in[9];
    const float* w_sel  = (const float*)d_in[10];
    const float* b_sel  = (const float*)d_in[11];
    float* out = (float*)d_out;

    // device global addresses
    __half *xh, *w0h, *wh, *hh;
    float *hf;
    cudaGetSymbolAddress((void**)&xh,  g_xh);
    cudaGetSymbolAddress((void**)&w0h, g_w0h);
    cudaGetSymbolAddress((void**)&wh,  g_wh);
    cudaGetSymbolAddress((void**)&hh,  g_hh);
    cudaGetSymbolAddress((void**)&hf,  g_h);

    // fp32 -> fp16 conversions
    f2h_kernel<<<(MTOT * II / 4 + 255) / 256, 256>>>(x, xh, MTOT * II / 4);
    f2h_kernel<<<(SS * 768 * 256 / 4 + 255) / 256, 256>>>(w_ih0, w0h, SS * 768 * 256 / 4);
    f2h_kernel<<<(SS * 3 * 768 * 256 / 4 + 255) / 256, 256>>>(w_ih, wh, SS * 3 * 768 * 256 / 4);

    cudaFuncSetAttribute(gru_mma_kernel,
                         cudaFuncAttributeMaxDynamicSharedMemorySize, SM_TOTAL);

    const dim3 gGemm(MTOT / 256, HH / 32, SS);
    const size_t hstride = (size_t)LL * MTOT * HH;

    // layer 0: A = xh (shared across s: sAs = 0), W = w0h
    gru_mma_kernel<<<gGemm, 256, SM_TOTAL>>>(
        xh, 0, w0h, (long long)768 * 256,
        b_ih0, b_hh0, 768,
        hf + 0 * (size_t)MTOT * HH, hh + 0 * (size_t)MTOT * HH);
    // layers 1..3: A = hh[s][l-1] (stride hstride), W = wh[s][l-1]
    for (int l = 1; l < LL; l++) {
        gru_mma_kernel<<<gGemm, 256, SM_TOTAL>>>(
            hh + (size_t)(l - 1) * MTOT * HH, (long long)hstride,
            wh + (size_t)(l - 1) * 768 * 256, (long long)3 * 768 * 256,
            b_ih + (size_t)(l - 1) * 768,
            b_hh + (size_t)(l - 1) * 768, 3 * 768,
            hf + (size_t)l * MTOT * HH, hh + (size_t)l * MTOT * HH);
    }

    xproj_kernel<<<255, 256>>>(x, w_sel, b_sel);
    table_kernel<<<dim3(255, 3), 256>>>(hidden, w_lw, b_lw, w_sel);
    serial_kernel<<<1, 256>>>();

    const long long n = (long long)out_size;
    const int nb = (int)((n + 255) / 256);
    gather_kernel<<<nb, 256>>>(out, n);
}

// round 6
// speedup vs baseline: 4.1724x; 1.0928x over previous
#include <cuda_runtime.h>
#include <cuda_fp16.h>
#include <cstdint>

// Problem constants
#define BB 128
#define TT 256
#define II 256
#define HH 256
#define LL 4
#define SS 3
#define KK 256
#define MTOT (BB*TT)

// Scratch
__device__ float  g_h [(size_t)SS * LL * MTOT * HH];  // fp32 h (outputs/gather)
__device__ __half g_hh[(size_t)SS * LL * MTOT * HH];  // fp16 h (GEMM A / table)
__device__ __half g_xh[(size_t)MTOT * II];            // fp16 x
__device__ __half g_w0h[(size_t)SS * 768 * 256];      // fp16 w_ih0
__device__ __half g_wh [(size_t)SS * 3 * 768 * 256];  // fp16 w_ih
__device__ float g_tabctx[255 * 3 * 3];
__device__ float g_xproj[256 * 3];
__device__ int   g_cur[256];

__device__ __forceinline__ float sigf(float x) {
    return __fdividef(1.f, 1.f + __expf(-x));
}
__device__ __forceinline__ uint32_t smem_u32(const void* p) {
    uint32_t a;
    asm("{ .reg .u64 t; cvta.to.shared.u64 t, %1; cvt.u32.u64 %0, t; }" : "=r"(a) : "l"(p));
    return a;
}
__device__ __forceinline__ void mma_f16(float* c, const uint32_t* a, const uint32_t* b) {
    asm volatile(
        "mma.sync.aligned.m16n8k16.row.col.f32.f16.f16.f32 "
        "{%0,%1,%2,%3}, {%4,%5,%6,%7}, {%8,%9}, {%0,%1,%2,%3};"
        : "+f"(c[0]), "+f"(c[1]), "+f"(c[2]), "+f"(c[3])
        : "r"(a[0]), "r"(a[1]), "r"(a[2]), "r"(a[3]), "r"(b[0]), "r"(b[1]));
}
#define LDSM4(r0, r1, r2, r3, addr) \
    asm volatile("ldmatrix.sync.aligned.m8n8.x4.shared.b16 {%0,%1,%2,%3}, [%4];" \
        : "=r"(r0), "=r"(r1), "=r"(r2), "=r"(r3) : "r"(addr))
#define CP16(dst, src) \
    asm volatile("cp.async.cg.shared.global [%0], [%1], 16;" :: "r"(dst), "l"(src))
#define CP_COMMIT() asm volatile("cp.async.commit_group;" ::: "memory")
#define CP_WAIT1()  asm volatile("cp.async.wait_group 1;" ::: "memory")

// SMEM: 3 stages x (A[128][64]h + W[96][64]h) + bias
//   stage = 128*128 + 96*128 = 28672 B; 3 stages = 86016; bias @ 86016
//   epilogue D overlay [128][100] f32 = 51200 (fits in stage region)
#define STAGE_BYTES 28672
#define W_OFF       16384
#define SM_BIAS     86016
#define SM_TOTAL    86528
#define DSTRIDE 100

// ---------------------------------------------------------------------------
// fp16 mma.sync GEMM + fused GRU gating.
// CTA: 128 M x 96 N (3 gates x 32 h). 8 warps (4m x 2n), warp tile 32x48.
// 2 CTAs/SM for cross-CTA load/epilogue/MMA overlap.
// K pipelined in 4 chunks of 64 via cp.async (3-stage); XOR-swizzled SMEM;
// ldmatrix.x4 fragments.
// ---------------------------------------------------------------------------
__global__ void __launch_bounds__(256, 2)
gru_mma_kernel(const __half* __restrict__ Ag, long long sAs,
               const __half* __restrict__ Wg, long long sWs,
               const float* __restrict__ BIg, const float* __restrict__ BHg, int sBs,
               float* __restrict__ Og, __half* __restrict__ Ohg)
{
    extern __shared__ char smem[];
    const uint32_t sbase = smem_u32(smem);
    float* sbias = (float*)(smem + SM_BIAS);
    float* Dsm   = (float*)smem;

    const int tid = threadIdx.x;
    const int wid = tid >> 5;
    const int lane = tid & 31;
    const int lq = lane >> 2;
    const int lr = lane & 3;

    const int s = blockIdx.z;
    const __half* A = Ag + (size_t)s * sAs;
    const __half* W = Wg + (size_t)s * sWs;
    const float* BI = BIg + s * sBs;
    const float* BH = BHg + s * sBs;
    float*  O  = Og  + (size_t)s * ((size_t)LL * MTOT * HH);
    __half* Oh = Ohg + (size_t)s * ((size_t)LL * MTOT * HH);

    const int mBase = blockIdx.x * 128;
    const int hb = blockIdx.y * 32;

    const int wm = (wid & 3) * 32;   // warp M offset (4 warps over 128 rows)
    const int wn = (wid >> 2) * 48;  // warp N offset (2 warps over 96 cols)

    // bias
    if (tid < 32)       sbias[tid] = __ldg(&BI[hb + tid])            + __ldg(&BH[hb + tid]);
    else if (tid < 64)  sbias[tid] = __ldg(&BI[256 + hb + tid - 32]) + __ldg(&BH[256 + hb + tid - 32]);
    else if (tid < 96)  sbias[tid] = __ldg(&BI[512 + hb + tid - 64]);
    else if (tid < 128) sbias[tid] = __ldg(&BH[512 + hb + tid - 96]);

    float acc[2][6][4];
#pragma unroll
    for (int mt = 0; mt < 2; mt++)
#pragma unroll
        for (int nt = 0; nt < 6; nt++)
#pragma unroll
            for (int q = 0; q < 4; q++) acc[mt][nt][q] = 0.f;

    // ---- stage loader: rows of 64 halves (128 B = 8 x 16B segs), XOR swizzle ----
    const int arow = tid >> 3;   // 0..31
    const int seg  = tid & 7;    // 16B segment id
    auto load_stage = [&](int buf, int k0) {
        const uint32_t stA = sbase + buf * STAGE_BYTES;
#pragma unroll
        for (int j = 0; j < 4; ++j) {
            const int row = arow + 32 * j;
            const uint32_t dst = stA + row * 128 + ((seg ^ (row & 7)) * 16);
            CP16(dst, A + (size_t)(mBase + row) * KK + k0 + seg * 8);
        }
#pragma unroll
        for (int j = 0; j < 3; ++j) {
            const int n = arow + 32 * j;                     // 0..95
            const int grow = (n >> 5) * 256 + hb + (n & 31); // gate-gathered W row
            const uint32_t dst = stA + W_OFF + n * 128 + ((seg ^ (n & 7)) * 16);
            CP16(dst, W + (size_t)grow * KK + k0 + seg * 8);
        }
    };

    // fragment addressing (per-lane constants)
    const int rA_lo = lane & 15;       // row offset within m16 tile
    const int sA    = lane >> 4;       // 0/1: k-seg select
    const int rB_lo = ((lane >> 4) << 3) + (lane & 7);  // n offset within n16 pair
    const int sB    = (lane >> 3) & 1;

    load_stage(0, 0);   CP_COMMIT();
    load_stage(1, 64);  CP_COMMIT();

#pragma unroll 1
    for (int st = 0; st < 4; ++st) {
        CP_WAIT1();
        __syncthreads();

        const int buf = st % 3;
        const uint32_t stA = sbase + buf * STAGE_BYTES;
        const uint32_t stW = stA + W_OFF;

#pragma unroll
        for (int kk = 0; kk < 4; ++kk) {
            uint32_t a[2][4];
#pragma unroll
            for (int mt = 0; mt < 2; mt++) {
                const int row = wm + mt * 16 + rA_lo;
                const uint32_t addr = stA + row * 128
                                    + (((kk * 2 + sA) ^ (row & 7)) * 16);
                LDSM4(a[mt][0], a[mt][1], a[mt][2], a[mt][3], addr);
            }
            uint32_t b[6][2];
#pragma unroll
            for (int np = 0; np < 3; np++) {
                const int n = wn + np * 16 + rB_lo;
                const uint32_t addr = stW + n * 128
                                    + (((kk * 2 + sB) ^ (n & 7)) * 16);
                uint32_t r0, r1, r2, r3;
                LDSM4(r0, r1, r2, r3, addr);
                b[2 * np][0] = r0; b[2 * np][1] = r1;
                b[2 * np + 1][0] = r2; b[2 * np + 1][1] = r3;
            }
#pragma unroll
            for (int mt = 0; mt < 2; mt++)
#pragma unroll
                for (int nt = 0; nt < 6; nt++)
                    mma_f16(acc[mt][nt], a[mt], b[nt]);
        }

        if (st + 2 < 4) load_stage((st + 2) % 3, (st + 2) * 64);
        CP_COMMIT();
    }

    __syncthreads();   // pipeline done; overlay D on stage buffers

    // accumulators -> SMEM D [128][100]
#pragma unroll
    for (int mt = 0; mt < 2; mt++) {
#pragma unroll
        for (int nt = 0; nt < 6; nt++) {
            const int row = wm + mt * 16 + lq;
            const int col = wn + nt * 8 + 2 * lr;
            *(float2*)(Dsm + row * DSTRIDE + col) =
                make_float2(acc[mt][nt][0], acc[mt][nt][1]);
            *(float2*)(Dsm + (row + 8) * DSTRIDE + col) =
                make_float2(acc[mt][nt][2], acc[mt][nt][3]);
        }
    }
    __syncthreads();

    // gate + coalesced dual store (fp32 + fp16-rna): 128 rows x 32 h
#pragma unroll
    for (int jj = 0; jj < 16; ++jj) {
        const int idx = tid + 256 * jj;
        const int m = idx >> 5;
        const int hl = idx & 31;
        const float gr = Dsm[m * DSTRIDE + hl]      + sbias[hl];
        const float gz = Dsm[m * DSTRIDE + 32 + hl] + sbias[32 + hl];
        const float gn = Dsm[m * DSTRIDE + 64 + hl] + sbias[64 + hl];
        const float r = sigf(gr);
        const float z = sigf(gz);
        const float n = 2.f * sigf(2.f * (gn + r * sbias[96 + hl])) - 1.f;
        const float hv = (1.f - z) * n;
        O [(size_t)(mBase + m) * HH + hb + hl] = hv;
        Oh[(size_t)(mBase + m) * HH + hb + hl] = __float2half_rn(hv);
    }
}

// ---------------------------------------------------------------------------
// fp32 -> fp16 (rna) conversion, vectorized x4
// ---------------------------------------------------------------------------
__global__ __launch_bounds__(256)
void f2h_kernel(const float* __restrict__ src, __half* __restrict__ dst, int n4)
{
    const int i = blockIdx.x * 256 + threadIdx.x;
    if (i < n4) {
        const float4 v = __ldg((const float4*)src + i);
        __half2* d = (__half2*)dst + 2 * i;
        d[0] = __floats2half2_rn(v.x, v.y);
        d[1] = __floats2half2_rn(v.z, v.w);
    }
}

// ---------------------------------------------------------------------------
// Attention/selection table (reads fp16 h copy)
// ---------------------------------------------------------------------------
__global__ __launch_bounds__(256)
void table_kernel(const float* __restrict__ hidden,
                  const float* __restrict__ w_lw,
                  const float* __restrict__ b_lw,
                  const float* __restrict__ w_sel)
{
    const int t = blockIdx.x;
    const int s = blockIdx.y;
    const int tid = threadIdx.x;
    const int lane = tid & 31;
    const int wp = tid >> 5;

    __shared__ float ep[512][8];
    __shared__ float red[4][3];

    float wr[7][8];
#pragma unroll
    for (int q = 0; q < 7; q++)
#pragma unroll
        for (int j = 0; j < 8; j++) {
            const int idx = lane + 32 * j;
            wr[q][j] = (q < 4) ? __ldg(&w_lw[q * 256 + idx])
                               : __ldg(&w_sel[(q - 4) * 512 + idx]);
        }

    for (int p = wp; p < 512; p += 8) {
        const int b = p >> 2, l = p & 3;
        const __half* hr = g_hh + ((size_t)(s * LL + l) * MTOT + (size_t)b * TT + t) * HH;
        float acc[7] = {0, 0, 0, 0, 0, 0, 0};
#pragma unroll
        for (int j = 0; j < 8; j++) {
            const float hv = __half2float(__ldg(&hr[lane + 32 * j]));
#pragma unroll
            for (int q = 0; q < 7; q++) acc[q] += hv * wr[q][j];
        }
#pragma unroll
        for (int q = 0; q < 7; q++) {
#pragma unroll
            for (int off = 16; off; off >>= 1)
                acc[q] += __shfl_xor_sync(0xffffffffu, acc[q], off);
        }
        if (lane < 7) ep[p][lane] = acc[lane];
    }
    __syncthreads();

    float sc[3] = {0.f, 0.f, 0.f};
    if (tid < 128) {
        const int b = tid;
        float bl[4];
#pragma unroll
        for (int lp = 0; lp < 4; lp++) bl[lp] = __ldg(&b_lw[lp]);
        float attn[4];
#pragma unroll
        for (int l = 0; l < 4; l++) {
            float a = 0.f;
#pragma unroll
            for (int lp = 0; lp < 4; lp++)
                a += __ldg(&hidden[b * 16 + l * 4 + lp]) * (ep[b * 4 + l][lp] + bl[lp]);
            attn[l] = a;
        }
        const float mx = fmaxf(fmaxf(attn[0], attn[1]), fmaxf(attn[2], attn[3]));
        float ee[4], ssum = 0.f;
#pragma unroll
        for (int l = 0; l < 4; l++) { ee[l] = __expf(attn[l] - mx); ssum += ee[l]; }
        const float inv = 1.f / ssum;
#pragma unroll
        for (int l = 0; l < 4; l++) {
            const float a = ee[l] * inv;
#pragma unroll
            for (int q = 0; q < 3; q++) sc[q] += a * ep[b * 4 + l][4 + q];
        }
#pragma unroll
        for (int q = 0; q < 3; q++)
#pragma unroll
            for (int off = 16; off; off >>= 1)
                sc[q] += __shfl_xor_sync(0xffffffffu, sc[q], off);
        if (lane == 0) { red[wp][0] = sc[0]; red[wp][1] = sc[1]; red[wp][2] = sc[2]; }
    }
    __syncthreads();
    if (tid < 3) {
        const float v = red[0][tid] + red[1][tid] + red[2][tid] + red[3][tid];
        g_tabctx[(t * 3 + s) * 3 + tid] = v;
    }
}

__global__ __launch_bounds__(256)
void xproj_kernel(const float* __restrict__ x,
                  const float* __restrict__ w_sel,
                  const float* __restrict__ b_sel)
{
    const int tau = blockIdx.x + 1;
    const int tid = threadIdx.x;
    const int lane = tid & 31, wp = tid >> 5;
    __shared__ float red[3][8];
    float xs = 0.f;
    const float* xp = x + (size_t)tau * II + tid;
#pragma unroll 4
    for (int b = 0; b < 128; b++) xs += __ldg(&xp[(size_t)b * TT * II]);
    float sc[3];
#pragma unroll
    for (int q = 0; q < 3; q++) sc[q] = xs * __ldg(&w_sel[q * 512 + 256 + tid]);
#pragma unroll
    for (int q = 0; q < 3; q++)
#pragma unroll
        for (int off = 16; off; off >>= 1)
            sc[q] += __shfl_xor_sync(0xffffffffu, sc[q], off);
    if (lane == 0) { red[0][wp] = sc[0]; red[1][wp] = sc[1]; red[2][wp] = sc[2]; }
    __syncthreads();
    if (tid < 3) {
        float v = 0.f;
#pragma unroll
        for (int w2 = 0; w2 < 8; w2++) v += red[tid][w2];
        g_xproj[tau * 3 + tid] = v + 128.f * __ldg(&b_sel[tid]);
    }
}

__global__ void serial_kernel()
{
    __shared__ float tab[255 * 9];
    __shared__ float xp[256 * 3];
    const int tid = threadIdx.x;
    for (int i = tid; i < 255 * 9; i += 256) tab[i] = g_tabctx[i];
    for (int i = tid; i < 256 * 3; i += 256) xp[i] = g_xproj[i];
    __syncthreads();
    if (tid == 0) {
        g_cur[0] = 0;
        int cur = 0;
        for (int tau = 1; tau < 256; tau++) {
            const float* tv = &tab[((tau - 1) * 3 + cur) * 3];
            const float v0 = tv[0] + xp[tau * 3 + 0];
            const float v1 = tv[1] + xp[tau * 3 + 1];
            const float v2 = tv[2] + xp[tau * 3 + 2];
            int c = 0; float best = v0;
            if (v1 > best) { best = v1; c = 1; }
            if (v2 > best) { best = v2; c = 2; }
            cur = c; g_cur[tau] = c;
        }
    }
}

__global__ __launch_bounds__(256)
void gather_kernel(float* __restrict__ out, long long n)
{
    const long long idx = (long long)blockIdx.x * 256 + threadIdx.x;
    if (idx >= n) return;
    const long long BTH = (long long)BB * TT * HH;
    int b, t, h;
    if (idx < BTH) {
        b = (int)(idx >> 16);
        const int r = (int)(idx & 65535);
        t = r >> 8; h = r & 255;
    } else {
        const long long j = idx - BTH;
        if (j >= (long long)BB * HH) { out[idx] = 0.f; return; }
        b = (int)(j >> 8); h = (int)(j & 255); t = TT - 1;
    }
    const int cur = g_cur[t];
    out[idx] = g_h[((size_t)(cur * LL + (LL - 1)) * MTOT + (size_t)b * TT + t) * HH + h];
}

// ---------------------------------------------------------------------------
extern "C" void kernel_launch(void* const* d_in, const int* in_sizes, int n_in,
                              void* d_out, int out_size)
{
    (void)in_sizes; (void)n_in;
    const float* x      = (const float*)d_in[0];
    const float* hidden = (const float*)d_in[1];
    const float* w_ih0  = (const float*)d_in[2];
    const float* b_ih0  = (const float*)d_in[3];
    const float* b_hh0  = (const float*)d_in[4];
    const float* w_ih   = (const float*)d_in[5];
    const float* b_ih   = (const float*)d_in[6];
    const float* b_hh   = (const float*)d_in[7];
    const float* w_lw   = (const float*)d_in[8];
    const float* b_lw   = (const float*)d_in[9];
    const float* w_sel  = (const float*)d_in[10];
    const float* b_sel  = (const float*)d_in[11];
    float* out = (float*)d_out;

    // device global addresses
    __half *xh, *w0h, *wh, *hh;
    float *hf;
    cudaGetSymbolAddress((void**)&xh,  g_xh);
    cudaGetSymbolAddress((void**)&w0h, g_w0h);
    cudaGetSymbolAddress((void**)&wh,  g_wh);
    cudaGetSymbolAddress((void**)&hh,  g_hh);
    cudaGetSymbolAddress((void**)&hf,  g_h);

    // fp32 -> fp16 conversions
    f2h_kernel<<<(MTOT * II / 4 + 255) / 256, 256>>>(x, xh, MTOT * II / 4);
    f2h_kernel<<<(SS * 768 * 256 / 4 + 255) / 256, 256>>>(w_ih0, w0h, SS * 768 * 256 / 4);
    f2h_kernel<<<(SS * 3 * 768 * 256 / 4 + 255) / 256, 256>>>(w_ih, wh, SS * 3 * 768 * 256 / 4);

    cudaFuncSetAttribute(gru_mma_kernel,
                         cudaFuncAttributeMaxDynamicSharedMemorySize, SM_TOTAL);

    const dim3 gGemm(MTOT / 128, HH / 32, SS);
    const size_t hstride = (size_t)LL * MTOT * HH;

    // layer 0: A = xh (shared across s: sAs = 0), W = w0h
    gru_mma_kernel<<<gGemm, 256, SM_TOTAL>>>(
        xh, 0, w0h, (long long)768 * 256,
        b_ih0, b_hh0, 768,
        hf + 0 * (size_t)MTOT * HH, hh + 0 * (size_t)MTOT * HH);
    // layers 1..3: A = hh[s][l-1] (stride hstride), W = wh[s][l-1]
    for (int l = 1; l < LL; l++) {
        gru_mma_kernel<<<gGemm, 256, SM_TOTAL>>>(
            hh + (size_t)(l - 1) * MTOT * HH, (long long)hstride,
            wh + (size_t)(l - 1) * 768 * 256, (long long)3 * 768 * 256,
            b_ih + (size_t)(l - 1) * 768,
            b_hh + (size_t)(l - 1) * 768, 3 * 768,
            hf + (size_t)l * MTOT * HH, hh + (size_t)l * MTOT * HH);
    }

    xproj_kernel<<<255, 256>>>(x, w_sel, b_sel);
    table_kernel<<<dim3(255, 3), 256>>>(hidden, w_lw, b_lw, w_sel);
    serial_kernel<<<1, 256>>>();

    const long long n = (long long)out_size;
    const int nb = (int)((n + 255) / 256);
    gather_kernel<<<nb, 256>>>(out, n);
}